// round 8
// baseline (speedup 1.0000x reference)
#include <cuda_runtime.h>

#define B_   32
#define T_   256
#define F_   64
#define C_   16
#define CO_  16
#define P_   64
#define S_   32
#define K_   4
#define FC   1024
#define KIN  1056
#define OUTC 96
#define ROWS (B_*T_)        // 8192
#define RSTR (F_*OUTC)      // 6144 floats per (b,t) row

// ---------------- packed f32x2 helpers ----------------
__device__ __forceinline__ double pack2(float lo, float hi) {
    double d; asm("mov.b64 %0, {%1, %2};" : "=d"(d) : "f"(lo), "f"(hi)); return d;
}
__device__ __forceinline__ float2 unpack2(double d) {
    float2 v; asm("mov.b64 {%0, %1}, %2;" : "=f"(v.x), "=f"(v.y) : "d"(d)); return v;
}
__device__ __forceinline__ void fma2(double& acc, double a, double b) {
    asm("fma.rn.f32x2 %0, %1, %2, %3;" : "=d"(acc) : "d"(a), "d"(b), "d"(acc));
}

struct SmemG {                                     // GEMM role: 16.7 KB
    alignas(16) double Ad[32][33];                 // [kk][m] dup doubles
    alignas(16) float  Bsf[32][64];                // [kk][n] natural pairs
};
struct SmemGP {                                    // overlays SmemG after last sync
    alignas(16) float gp[32][64];                  // relu(point_out) tile, 8 KB
};
struct SmemC {                                     // conv role: 23 KB
    alignas(16) float xs[T_ + 6][17];
    alignas(16) float ws[64][20];
    alignas(16) float bsv[16];
};
union SmemU { SmemG g; SmemGP p; SmemC c; };

// ============================================================================
// Single fused kernel. blockIdx % 9 == 0 -> GEMM role (256 blocks):
//   point GEMM (BM=32,BN=64,BK=32, pack-over-N) + direct broadcast of
//   ch32..95 to all 64 features. Otherwise conv role (2048 blocks):
//   causal dilated conv -> ch16..31, plus relu(x) stream -> ch0..15.
// ============================================================================
__global__ __launch_bounds__(256)
void tpc_all(const float* __restrict__ x,
             const float* __restrict__ stat,
             const float* __restrict__ conv_w,
             const float* __restrict__ conv_b,
             const float* __restrict__ W_p,
             const float* __restrict__ b_p,
             float* __restrict__ out)
{
    __shared__ SmemU sm;
    const int tid  = threadIdx.x;
    const int grp  = blockIdx.x / 9;
    const int role = blockIdx.x - grp * 9;

    if (role == 0) {
        // ======================= GEMM ROLE =======================
        const int row0 = grp * 32;
        const int b    = row0 >> 8;
        const int m0   = (tid >> 4) * 2;
        const int ng   = tid & 15;

        const int ar  = tid >> 3;
        const int akq = tid & 7;
        const int bkk = tid >> 4;
        const int bnq = tid & 15;

        double acc0 = 0.0, acc1 = 0.0, acc2 = 0.0, acc3 = 0.0;
        float4 pa, pb0, pb1;

        pa  = *reinterpret_cast<const float4*>(&x[(size_t)(row0 + ar) * FC + akq * 4]);
        pb0 = *reinterpret_cast<const float4*>(&W_p[(size_t)bkk * P_ + bnq * 4]);
        pb1 = *reinterpret_cast<const float4*>(&W_p[(size_t)(bkk + 16) * P_ + bnq * 4]);

        for (int kb = 0; kb < 33; ++kb) {
            sm.g.Ad[akq * 4 + 0][ar] = pack2(pa.x, pa.x);
            sm.g.Ad[akq * 4 + 1][ar] = pack2(pa.y, pa.y);
            sm.g.Ad[akq * 4 + 2][ar] = pack2(pa.z, pa.z);
            sm.g.Ad[akq * 4 + 3][ar] = pack2(pa.w, pa.w);
            *reinterpret_cast<float4*>(&sm.g.Bsf[bkk][bnq * 4])      = pb0;
            *reinterpret_cast<float4*>(&sm.g.Bsf[bkk + 16][bnq * 4]) = pb1;
            __syncthreads();

            if (kb < 32) {
                int kg0 = (kb + 1) * 32;
                int kgf = kg0 + akq * 4;
                if (kgf < FC)
                    pa = *reinterpret_cast<const float4*>(&x[(size_t)(row0 + ar) * FC + kgf]);
                else
                    pa = *reinterpret_cast<const float4*>(&stat[b * S_ + (kgf - FC)]);
                pb0 = *reinterpret_cast<const float4*>(&W_p[(size_t)(kg0 + bkk) * P_ + bnq * 4]);
                pb1 = *reinterpret_cast<const float4*>(&W_p[(size_t)(kg0 + bkk + 16) * P_ + bnq * 4]);
            }

            #pragma unroll
            for (int kk = 0; kk < 32; ++kk) {
                double a0 = sm.g.Ad[kk][m0];
                double a1 = sm.g.Ad[kk][m0 + 1];
                const double* brow = reinterpret_cast<const double*>(&sm.g.Bsf[kk][0]);
                double b0 = brow[ng];
                double b1 = brow[ng + 16];
                fma2(acc0, a0, b0);
                fma2(acc1, a0, b1);
                fma2(acc2, a1, b0);
                fma2(acc3, a1, b1);
            }
            __syncthreads();
        }

        // epilogue: bias + relu -> smem gp tile (overlays Ad; synced above)
        {
            float2 bb0 = *reinterpret_cast<const float2*>(&b_p[2 * ng]);
            float2 bb1 = *reinterpret_cast<const float2*>(&b_p[2 * ng + 32]);
            float2 p;
            p = unpack2(acc0);
            *reinterpret_cast<float2*>(&sm.p.gp[m0][2 * ng]) =
                make_float2(fmaxf(p.x + bb0.x, 0.f), fmaxf(p.y + bb0.y, 0.f));
            p = unpack2(acc1);
            *reinterpret_cast<float2*>(&sm.p.gp[m0][2 * ng + 32]) =
                make_float2(fmaxf(p.x + bb1.x, 0.f), fmaxf(p.y + bb1.y, 0.f));
            p = unpack2(acc2);
            *reinterpret_cast<float2*>(&sm.p.gp[m0 + 1][2 * ng]) =
                make_float2(fmaxf(p.x + bb0.x, 0.f), fmaxf(p.y + bb0.y, 0.f));
            p = unpack2(acc3);
            *reinterpret_cast<float2*>(&sm.p.gp[m0 + 1][2 * ng + 32]) =
                make_float2(fmaxf(p.x + bb1.x, 0.f), fmaxf(p.y + bb1.y, 0.f));
        }
        __syncthreads();

        // broadcast ch32..95 for 32 rows x 64 features: 32768 float4
        #pragma unroll 4
        for (int l = 0; l < 128; ++l) {
            int flat = l * 256 + tid;
            int q = flat & 15;
            int f = (flat >> 4) & 63;
            int r = flat >> 10;
            float4 v = *reinterpret_cast<const float4*>(&sm.p.gp[r][q * 4]);
            *reinterpret_cast<float4*>(
                &out[(size_t)(row0 + r) * RSTR + f * OUTC + 32 + q * 4]) = v;
        }
    } else {
        // ======================= CONV ROLE =======================
        const int cb = grp * 8 + (role - 1);       // 0..2047
        const int b  = cb >> 6;
        const int f  = cb & 63;
        const size_t xrow0 = ((size_t)b * T_ * F_ + f) * C_;

        // x slab (rows 0..5 zero pad; row r -> t = r-6)
        #pragma unroll
        for (int l = 0; l < 5; ++l) {
            int idx = tid + l * 256;
            if (idx < (T_ + 6) * 4) {
                int r = idx >> 2;
                int q = idx & 3;
                float4 v = make_float4(0.f, 0.f, 0.f, 0.f);
                if (r >= 6)
                    v = *reinterpret_cast<const float4*>(&x[xrow0 + (size_t)(r - 6) * FC + q * 4]);
                sm.c.xs[r][q * 4 + 0] = v.x;
                sm.c.xs[r][q * 4 + 1] = v.y;
                sm.c.xs[r][q * 4 + 2] = v.z;
                sm.c.xs[r][q * 4 + 3] = v.w;
            }
        }
        // weights transposed to [ck][co]
        {
            int co = tid >> 4;
            int c  = tid & 15;
            float4 w = *reinterpret_cast<const float4*>(&conv_w[((size_t)f * CO_ + co) * 64 + c * 4]);
            sm.c.ws[c * 4 + 0][co] = w.x;
            sm.c.ws[c * 4 + 1][co] = w.y;
            sm.c.ws[c * 4 + 2][co] = w.z;
            sm.c.ws[c * 4 + 3][co] = w.w;
        }
        if (tid < 16) sm.c.bsv[tid] = conv_b[f * CO_ + tid];
        __syncthreads();

        const int t0  = (tid >> 2) * 4;
        const int co0 = (tid & 3) * 4;

        double acc[4][2];
        #pragma unroll
        for (int i = 0; i < 4; ++i) { acc[i][0] = 0.0; acc[i][1] = 0.0; }

        #pragma unroll 4
        for (int c = 0; c < C_; ++c) {
            double ad[10];
            #pragma unroll
            for (int r = 0; r < 10; ++r) {
                float a = sm.c.xs[t0 + r][c];
                ad[r] = pack2(a, a);
            }
            #pragma unroll
            for (int k = 0; k < K_; ++k) {
                double2 w = *reinterpret_cast<const double2*>(&sm.c.ws[c * 4 + k][co0]);
                #pragma unroll
                for (int i = 0; i < 4; ++i) {
                    fma2(acc[i][0], ad[i + 2 * k], w.x);
                    fma2(acc[i][1], ad[i + 2 * k], w.y);
                }
            }
        }

        float* ob = out + ((size_t)b * T_ * F_ + f) * OUTC;

        // ch16..31 from registers
        {
            float4 bb = *reinterpret_cast<const float4*>(&sm.c.bsv[co0]);
            #pragma unroll
            for (int i = 0; i < 4; ++i) {
                float2 q0 = unpack2(acc[i][0]);
                float2 q1 = unpack2(acc[i][1]);
                float4 v = make_float4(fmaxf(q0.x + bb.x, 0.f), fmaxf(q0.y + bb.y, 0.f),
                                       fmaxf(q1.x + bb.z, 0.f), fmaxf(q1.y + bb.w, 0.f));
                *reinterpret_cast<float4*>(&ob[(size_t)(t0 + i) * RSTR + 16 + co0]) = v;
            }
        }

        // ch0..15 = relu(x), re-read from L2-hot x (1024 float4)
        #pragma unroll
        for (int l = 0; l < 4; ++l) {
            int idx = tid + l * 256;
            int t   = idx >> 2;
            int q   = idx & 3;
            float4 v = *reinterpret_cast<const float4*>(&x[xrow0 + (size_t)t * FC + q * 4]);
            v.x = fmaxf(v.x, 0.f); v.y = fmaxf(v.y, 0.f);
            v.z = fmaxf(v.z, 0.f); v.w = fmaxf(v.w, 0.f);
            *reinterpret_cast<float4*>(&ob[(size_t)t * RSTR + q * 4]) = v;
        }
    }
}

extern "C" void kernel_launch(void* const* d_in, const int* in_sizes, int n_in,
                              void* d_out, int out_size)
{
    const float* x      = (const float*)d_in[0];   // [32,256,64,16]
    const float* statv  = (const float*)d_in[1];   // [32,32]
    const float* conv_w = (const float*)d_in[2];   // [64,16,16,4]
    const float* conv_b = (const float*)d_in[3];   // [64,16]
    const float* W_p    = (const float*)d_in[4];   // [1056,64]
    const float* b_p    = (const float*)d_in[5];   // [64]
    float* out = (float*)d_out;                    // [32,256,64,96]

    tpc_all<<<2304, 256>>>(x, statv, conv_w, conv_b, W_p, b_p, out);
}

// round 9
// speedup vs baseline: 1.4654x; 1.4654x over previous
#include <cuda_runtime.h>

#define B_   32
#define T_   256
#define F_   64
#define C_   16
#define CO_  16
#define P_   64
#define S_   32
#define K_   4
#define FC   1024
#define KIN  1056
#define OUTC 96
#define ROWS (B_*T_)        // 8192
#define RSTR (F_*OUTC)      // 6144 floats per (b,t) row

// split-K partial sums (no bias/relu yet): 2 x 8192 x 64 fp32 = 4 MB
__device__ __align__(256) float g_part[2][ROWS][P_];

// ---------------- packed f32x2 helpers ----------------
__device__ __forceinline__ double pack2(float lo, float hi) {
    double d; asm("mov.b64 %0, {%1, %2};" : "=d"(d) : "f"(lo), "f"(hi)); return d;
}
__device__ __forceinline__ float2 unpack2(double d) {
    float2 v; asm("mov.b64 {%0, %1}, %2;" : "=f"(v.x), "=f"(v.y) : "d"(d)); return v;
}
__device__ __forceinline__ void fma2(double& acc, double a, double b) {
    asm("fma.rn.f32x2 %0, %1, %2, %3;" : "=d"(acc) : "d"(a), "d"(b), "d"(acc));
}

// ============================================================================
// Kernel 1: split-K point GEMM. grid=512 (256 tiles x 2 K-halves), 128 thr.
// BM=32, BN=64, BK=32. Per-thread 4m x 4n: 3 LDS.128 : 8 FMA2 per kk.
// half 0: kb 0..16 (k 0..543), half 1: kb 17..32 (k 544..1055).
// ============================================================================
__global__ __launch_bounds__(128)
void tpc_gemm(const float* __restrict__ x,
              const float* __restrict__ stat,
              const float* __restrict__ W_p)
{
    __shared__ __align__(16) double Ad[32][34];   // [kk][m] dup doubles, 8.7 KB
    __shared__ __align__(16) float  Bsf[32][64];  // [kk][n] natural pairs, 8 KB

    const int tid  = threadIdx.x;
    const int tile = blockIdx.x >> 1;
    const int half = blockIdx.x & 1;
    const int row0 = tile * 32;
    const int b    = row0 >> 8;

    const int kb0 = half ? 17 : 0;
    const int kbE = half ? 33 : 17;      // exclusive end

    const int mg = tid >> 4;             // 0..7
    const int ng = tid & 15;             // 0..15
    const int m0 = mg * 4;
    const int n0 = ng * 4;

    // loader indices
    const int ar  = tid >> 3;            // 0..15 -> two passes cover 32 rows? no:
    // A tile: 256 float4 (32 rows x 8 k-quads), 2 per thread
    // B tile: 512 float4 (32 kk x 16 n-quads), 4 per thread
    const int akq = tid & 7;

    double acc[4][2];
    #pragma unroll
    for (int i = 0; i < 4; ++i) { acc[i][0] = 0.0; acc[i][1] = 0.0; }

    float4 pa[2], pb[4];

    // prefetch kb0 (kb0 tiles never touch the static columns: k < 1024)
    #pragma unroll
    for (int l = 0; l < 2; ++l) {
        int idx = tid + l * 128;
        int r   = idx >> 3;
        pa[l] = *reinterpret_cast<const float4*>(
            &x[(size_t)(row0 + r) * FC + kb0 * 32 + akq * 4]);
    }
    #pragma unroll
    for (int l = 0; l < 4; ++l) {
        int idx = tid + l * 128;
        int kk  = idx >> 4;
        int nq  = idx & 15;
        pb[l] = *reinterpret_cast<const float4*>(
            &W_p[(size_t)(kb0 * 32 + kk) * P_ + nq * 4]);
    }

    for (int kb = kb0; kb < kbE; ++kb) {
        // commit prefetched tiles to smem
        #pragma unroll
        for (int l = 0; l < 2; ++l) {
            int idx = tid + l * 128;
            int r   = idx >> 3;
            Ad[akq * 4 + 0][r] = pack2(pa[l].x, pa[l].x);
            Ad[akq * 4 + 1][r] = pack2(pa[l].y, pa[l].y);
            Ad[akq * 4 + 2][r] = pack2(pa[l].z, pa[l].z);
            Ad[akq * 4 + 3][r] = pack2(pa[l].w, pa[l].w);
        }
        #pragma unroll
        for (int l = 0; l < 4; ++l) {
            int idx = tid + l * 128;
            int kk  = idx >> 4;
            int nq  = idx & 15;
            *reinterpret_cast<float4*>(&Bsf[kk][nq * 4]) = pb[l];
        }
        __syncthreads();

        // prefetch next tile while computing
        if (kb + 1 < kbE) {
            int kg0 = (kb + 1) * 32;
            #pragma unroll
            for (int l = 0; l < 2; ++l) {
                int idx = tid + l * 128;
                int r   = idx >> 3;
                int kgf = kg0 + akq * 4;
                if (kgf < FC)
                    pa[l] = *reinterpret_cast<const float4*>(&x[(size_t)(row0 + r) * FC + kgf]);
                else
                    pa[l] = *reinterpret_cast<const float4*>(&stat[b * S_ + (kgf - FC)]);
            }
            #pragma unroll
            for (int l = 0; l < 4; ++l) {
                int idx = tid + l * 128;
                int kk  = idx >> 4;
                int nq  = idx & 15;
                pb[l] = *reinterpret_cast<const float4*>(
                    &W_p[(size_t)(kg0 + kk) * P_ + nq * 4]);
            }
        }

        #pragma unroll
        for (int kk = 0; kk < 32; ++kk) {
            double2 a01 = *reinterpret_cast<const double2*>(&Ad[kk][m0]);
            double2 a23 = *reinterpret_cast<const double2*>(&Ad[kk][m0 + 2]);
            double2 bp  = *reinterpret_cast<const double2*>(&Bsf[kk][n0]);
            fma2(acc[0][0], a01.x, bp.x); fma2(acc[0][1], a01.x, bp.y);
            fma2(acc[1][0], a01.y, bp.x); fma2(acc[1][1], a01.y, bp.y);
            fma2(acc[2][0], a23.x, bp.x); fma2(acc[2][1], a23.x, bp.y);
            fma2(acc[3][0], a23.y, bp.x); fma2(acc[3][1], a23.y, bp.y);
        }
        __syncthreads();
    }

    // store raw partials (bias/relu applied in kernel 2 after the K-halves add)
    #pragma unroll
    for (int m = 0; m < 4; ++m) {
        float2 p = unpack2(acc[m][0]);
        float2 q = unpack2(acc[m][1]);
        float4 v = make_float4(p.x, p.y, q.x, q.y);
        *reinterpret_cast<float4*>(&g_part[half][row0 + m0 + m][n0]) = v;
    }
}

// ============================================================================
// Kernel 2: interleaved roles. even blocks: conv (b,f) -> out ch16..31.
// odd blocks: stream ch0..15 (relu x) + ch32..95 (add K-halves + bias + relu,
// broadcast to all 64 features).
// ============================================================================
__global__ __launch_bounds__(256)
void tpc_fuse(const float* __restrict__ x,
              const float* __restrict__ conv_w,
              const float* __restrict__ conv_b,
              const float* __restrict__ b_p,
              float* __restrict__ out)
{
    __shared__ __align__(16) float xs[T_ + 6][17];  // conflict-free scalar reads
    __shared__ __align__(16) float ws[64][20];      // [c*4+k][co]
    __shared__ float bsv[16];

    const int tid = threadIdx.x;

    if ((blockIdx.x & 1) == 0) {
        // ---------------- CONV ROLE ----------------
        const int cb = blockIdx.x >> 1;
        const int b  = cb >> 6;
        const int f  = cb & 63;
        const size_t xrow0 = ((size_t)b * T_ * F_ + f) * C_;

        #pragma unroll
        for (int l = 0; l < 5; ++l) {
            int idx = tid + l * 256;
            if (idx < (T_ + 6) * 4) {
                int r = idx >> 2;
                int q = idx & 3;
                float4 v = make_float4(0.f, 0.f, 0.f, 0.f);
                if (r >= 6)
                    v = *reinterpret_cast<const float4*>(&x[xrow0 + (size_t)(r - 6) * FC + q * 4]);
                xs[r][q * 4 + 0] = v.x;
                xs[r][q * 4 + 1] = v.y;
                xs[r][q * 4 + 2] = v.z;
                xs[r][q * 4 + 3] = v.w;
            }
        }
        {
            int co = tid >> 4;
            int c  = tid & 15;
            float4 w = *reinterpret_cast<const float4*>(&conv_w[((size_t)f * CO_ + co) * 64 + c * 4]);
            ws[c * 4 + 0][co] = w.x;
            ws[c * 4 + 1][co] = w.y;
            ws[c * 4 + 2][co] = w.z;
            ws[c * 4 + 3][co] = w.w;
        }
        if (tid < 16) bsv[tid] = conv_b[f * CO_ + tid];
        __syncthreads();

        const int t0  = (tid >> 2) * 4;
        const int co0 = (tid & 3) * 4;

        double acc[4][2];
        #pragma unroll
        for (int i = 0; i < 4; ++i) { acc[i][0] = 0.0; acc[i][1] = 0.0; }

        #pragma unroll 4
        for (int c = 0; c < C_; ++c) {
            double ad[10];
            #pragma unroll
            for (int r = 0; r < 10; ++r) {
                float a = xs[t0 + r][c];
                ad[r] = pack2(a, a);
            }
            #pragma unroll
            for (int k = 0; k < K_; ++k) {
                double2 w = *reinterpret_cast<const double2*>(&ws[c * 4 + k][co0]);
                #pragma unroll
                for (int i = 0; i < 4; ++i) {
                    fma2(acc[i][0], ad[i + 2 * k], w.x);
                    fma2(acc[i][1], ad[i + 2 * k], w.y);
                }
            }
        }

        float4 bb = *reinterpret_cast<const float4*>(&bsv[co0]);
        float* ob = out + ((size_t)b * T_ * F_ + f) * OUTC;
        #pragma unroll
        for (int i = 0; i < 4; ++i) {
            float2 q0 = unpack2(acc[i][0]);
            float2 q1 = unpack2(acc[i][1]);
            float4 v = make_float4(fmaxf(q0.x + bb.x, 0.f), fmaxf(q0.y + bb.y, 0.f),
                                   fmaxf(q1.x + bb.z, 0.f), fmaxf(q1.y + bb.w, 0.f));
            *reinterpret_cast<float4*>(&ob[(size_t)(t0 + i) * RSTR + 16 + co0]) = v;
        }
    } else {
        // ---------------- STREAM ROLE ----------------
        const int rb = blockIdx.x >> 1;
        const int row_base = rb * 4;

        // ch 0..15: relu(x) (1024 float4)
        #pragma unroll
        for (int l = 0; l < 4; ++l) {
            int idx  = tid + l * 256;
            int r    = idx >> 8;
            int rest = idx & 255;
            int row  = row_base + r;
            float4 v = *reinterpret_cast<const float4*>(&x[(size_t)row * FC + rest * 4]);
            v.x = fmaxf(v.x, 0.f); v.y = fmaxf(v.y, 0.f);
            v.z = fmaxf(v.z, 0.f); v.w = fmaxf(v.w, 0.f);
            int f = rest >> 2;
            int q = rest & 3;
            *reinterpret_cast<float4*>(&out[(size_t)row * RSTR + f * OUTC + q * 4]) = v;
        }
        // ch 32..95: add K-halves + bias + relu, broadcast (4096 float4)
        const int q  = tid & 15;
        const int f0 = tid >> 4;
        float4 bb = *reinterpret_cast<const float4*>(&b_p[q * 4]);
        #pragma unroll
        for (int rr = 0; rr < 4; ++rr) {
            int row  = row_base + rr;
            float4 v0 = *reinterpret_cast<const float4*>(&g_part[0][row][q * 4]);
            float4 v1 = *reinterpret_cast<const float4*>(&g_part[1][row][q * 4]);
            float4 v;
            v.x = fmaxf(v0.x + v1.x + bb.x, 0.f);
            v.y = fmaxf(v0.y + v1.y + bb.y, 0.f);
            v.z = fmaxf(v0.z + v1.z + bb.z, 0.f);
            v.w = fmaxf(v0.w + v1.w + bb.w, 0.f);
            float* ob = out + (size_t)row * RSTR + 32 + q * 4;
            #pragma unroll
            for (int ff = 0; ff < 4; ++ff) {
                int f = ff * 16 + f0;
                *reinterpret_cast<float4*>(&ob[(size_t)f * OUTC]) = v;
            }
        }
    }
}

extern "C" void kernel_launch(void* const* d_in, const int* in_sizes, int n_in,
                              void* d_out, int out_size)
{
    const float* x      = (const float*)d_in[0];   // [32,256,64,16]
    const float* statv  = (const float*)d_in[1];   // [32,32]
    const float* conv_w = (const float*)d_in[2];   // [64,16,16,4]
    const float* conv_b = (const float*)d_in[3];   // [64,16]
    const float* W_p    = (const float*)d_in[4];   // [1056,64]
    const float* b_p    = (const float*)d_in[5];   // [64]
    float* out = (float*)d_out;                    // [32,256,64,96]

    tpc_gemm<<<512, 128>>>(x, statv, W_p);
    tpc_fuse<<<4096, 256>>>(x, conv_w, conv_b, b_p, out);
}